// round 11
// baseline (speedup 1.0000x reference)
#include <cuda_runtime.h>
#include <cuda_bf16.h>

// Fixed problem shape: B=8, R=C=1024, instance ids in [0,16).
static constexpr int RDIM = 1024;
static constexpr int CDIM = 1024;
static constexpr int PER_BATCH = RDIM * CDIM;            // 2^20 pixels
static constexpr int BATCH = 8;
static constexpr int MAX_INST = 16;
static constexpr int NPIX = BATCH * PER_BATCH;           // 2^23
static constexpr int NVEC_B = PER_BATCH / 4;             // 2^18 vec4 per batch

// Kernel 1: 256 threads x 4 vec4/thread, front-loaded loads (R6-proven).
static constexpr int TPB1 = 256;
static constexpr int VPT1 = 4;
static constexpr int VEC_PER_BLK1 = TPB1 * VPT1;                    // 1024
static constexpr int BLKS_PER_B = NVEC_B / VEC_PER_BLK1;            // 256
// Kernel 2 (main): 2 vec4/thread, batch-pure blocks.
static constexpr int TPB3 = 256;
static constexpr int VPT3 = 2;
static constexpr int GRID3 = (NPIX / 4) / (TPB3 * VPT3);            // 4096

// Scratch (static device globals; zero-initialized at module load).
// Invariant: g_cnt == 0 at the start of every kernel_launch execution —
// the LAST main block re-zeroes it after all blocks consumed it.
__device__ int                g_cnt[BATCH * MAX_INST];
__device__ unsigned long long g_done;          // monotone arrival counter
__device__ unsigned char      g_plane[NPIX];   // byte = raw_gt | (valid << 4)

__device__ __forceinline__ float sigmoidf_fast(float x) {
    return 1.0f / (1.0f + __expf(-x));
}

// ---- Kernel 1: counts (atomic accumulate) + combined byte plane ----
__global__ void __launch_bounds__(TPB1, 4) pc_count_kernel(
    const int* __restrict__ nz, const int* __restrict__ gt)
{
    __shared__ unsigned long long wcnt[TPB1 / 32][4];

    const int tid  = threadIdx.x;
    const int wid  = tid >> 5;
    const int lane = tid & 31;
    const int b    = blockIdx.y;
    const long long base = ((long long)b << 20)
                         + (long long)(blockIdx.x * VEC_PER_BLK1 + tid) * 4;

    // Front-load ALL global reads: 8 outstanding LDG.128 before any compute.
    int4 nzv[VPT1], gtv[VPT1];
    #pragma unroll
    for (int j = 0; j < VPT1; ++j) {
        const long long i0 = base + (long long)j * (TPB1 * 4);
        nzv[j] = *reinterpret_cast<const int4*>(nz + i0);
        gtv[j] = *reinterpret_cast<const int4*>(gt + i0);
    }

    // Two independent 4-bit-field accumulators (id*4 bit position).
    unsigned long long c01 = 0ULL, c23 = 0ULL;

    #pragma unroll
    for (int j = 0; j < VPT1; ++j) {
        const long long i0 = base + (long long)j * (TPB1 * 4);
        const unsigned g01 = __byte_perm((unsigned)gtv[j].x, (unsigned)gtv[j].y, 0x0040);
        const unsigned g23 = __byte_perm((unsigned)gtv[j].z, (unsigned)gtv[j].w, 0x0040);
        const unsigned gp  = __byte_perm(g01, g23, 0x5410);
        const unsigned n01 = __byte_perm((unsigned)nzv[j].x, (unsigned)nzv[j].y, 0x0040);
        const unsigned n23 = __byte_perm((unsigned)nzv[j].z, (unsigned)nzv[j].w, 0x0040);
        const unsigned np  = __byte_perm(n01, n23, 0x5410);

        const unsigned vmask = ((gp + 0x0F0F0F0Fu) & 0x10101010u) & (np << 4);
        *reinterpret_cast<unsigned int*>(g_plane + i0) = gp | vmask;

        const unsigned mg = gp & ((vmask >> 4) * 0xFFu);

        unsigned long long& c = (j < 2) ? c01 : c23;
        c += 1ULL << ((mg << 2) & 0x3Cu);
        c += 1ULL << ((mg >> 6) & 0x3Cu);
        c += 1ULL << ((mg >> 14) & 0x3Cu);
        c += 1ULL << ((mg >> 22) & 0x3Cu);
    }

    const unsigned long long M4 = 0x0F0F0F0F0F0F0F0FULL;
    const unsigned long long M8 = 0x00FF00FF00FF00FFULL;
    const unsigned long long A  = (c01 & M4) + (c23 & M4);
    const unsigned long long Bv = ((c01 >> 4) & M4) + ((c23 >> 4) & M4);
    unsigned long long v0 = A & M8;          // ids 0,4,8,12
    unsigned long long v1 = (A >> 8) & M8;   // ids 2,6,10,14
    unsigned long long v2 = Bv & M8;         // ids 1,5,9,13
    unsigned long long v3 = (Bv >> 8) & M8;  // ids 3,7,11,15

    #pragma unroll
    for (int s = 16; s > 0; s >>= 1) {
        v0 += __shfl_xor_sync(0xffffffffu, v0, s);
        v1 += __shfl_xor_sync(0xffffffffu, v1, s);
        v2 += __shfl_xor_sync(0xffffffffu, v2, s);
        v3 += __shfl_xor_sync(0xffffffffu, v3, s);
    }
    if (lane == 0) {
        wcnt[wid][0] = v0; wcnt[wid][1] = v1; wcnt[wid][2] = v2; wcnt[wid][3] = v3;
    }
    __syncthreads();

    if (tid < MAX_INST) {
        const int id = tid;
        const int vec   = (id & 1) ? ((id & 2) ? 3 : 2) : ((id & 2) ? 1 : 0);
        const int shift = (id >> 2) * 16;
        int s = 0;
        #pragma unroll
        for (int w = 0; w < TPB1 / 32; ++w)
            s += (int)((wcnt[w][vec] >> shift) & 0xFFFFULL);
        atomicAdd(&g_cnt[b * MAX_INST + id], s);   // L2-coherent; no fence needed
    }
}

// ---- Kernel 2: per-pixel weights; per-block inv table from g_cnt;
//      last block zeroes g_cnt for the next graph replay. ----
__global__ void __launch_bounds__(TPB3, 6) pc_main_kernel(
    const float* __restrict__ pred,
    const float* __restrict__ off,     // (B, 2, R, C)
    float*       __restrict__ out_pw,  // (B, R, C)
    float*       __restrict__ out_ow)  // (B, 2, R, C)
{
    __shared__ float inv_sh[MAX_INST];
    __shared__ bool  last;

    const int vblk = blockIdx.x * (TPB3 * VPT3);           // block never straddles a batch
    const int b    = vblk >> 18;                           // / (PER_BATCH/4)
    const unsigned rem0 = (unsigned)((vblk + threadIdx.x) << 2) & (PER_BATCH - 1);

    // Build this batch's inv table (one 64B L2-hot line).
    if (threadIdx.x < MAX_INST) {
        const int c = g_cnt[b * MAX_INST + threadIdx.x];
        inv_sh[threadIdx.x] = 1.0f / fmaxf((float)c, 1.0f);
    }
    __syncthreads();

    const float* __restrict__ pred_b   = pred   + ((long long)b << 20);
    const float* __restrict__ off_b    = off    + ((long long)b << 21);
    float*       __restrict__ out_pw_b = out_pw + ((long long)b << 20);
    float*       __restrict__ out_ow_b = out_ow + ((long long)b << 21);
    const unsigned char* __restrict__ plane_b = g_plane + ((long long)b << 20);

    // Stage 1: front-load all streaming reads (10 outstanding LDGs).
    unsigned int packed[VPT3];
    float4 pr4[VPT3], oy4[VPT3], ox4[VPT3];
    #pragma unroll
    for (int j = 0; j < VPT3; ++j) {
        const unsigned rem = rem0 + j * (TPB3 * 4);
        packed[j] = *reinterpret_cast<const unsigned int*>(plane_b + rem);
        oy4[j] = *reinterpret_cast<const float4*>(off_b + rem);
        ox4[j] = *reinterpret_cast<const float4*>(off_b + rem + PER_BATCH);
        pr4[j] = *reinterpret_cast<const float4*>(pred_b + rem);
    }

    // Stage 2: all 8 gather addresses, all gathers issued in parallel.
    unsigned tb[VPT3][4];
    #pragma unroll
    for (int j = 0; j < VPT3; ++j) {
        const unsigned rem = rem0 + j * (TPB3 * 4);
        const float rf = (float)(rem >> 10);
        const float cf = (float)(rem & (CDIM - 1));
        const float oys[4] = {oy4[j].x, oy4[j].y, oy4[j].z, oy4[j].w};
        const float oxs[4] = {ox4[j].x, ox4[j].y, ox4[j].z, ox4[j].w};
        #pragma unroll
        for (int k = 0; k < 4; ++k) {
            // round-half-to-even matches jnp.round
            float tyf = rintf(rf + oys[k]);
            float txf = rintf(cf + (float)k + oxs[k]);
            tyf = fminf(fmaxf(tyf, 0.0f), (float)(RDIM - 1));
            txf = fminf(fmaxf(txf, 0.0f), (float)(CDIM - 1));
            tb[j][k] = __ldg(&plane_b[((unsigned)tyf << 10) + (unsigned)txf]);
        }
    }

    // Stage 3: straight-line epilogue.
    #pragma unroll
    for (int j = 0; j < VPT3; ++j) {
        const unsigned rem = rem0 + j * (TPB3 * 4);
        const float prs[4] = {pr4[j].x, pr4[j].y, pr4[j].z, pr4[j].w};
        const float oys[4] = {oy4[j].x, oy4[j].y, oy4[j].z, oy4[j].w};
        const float oxs[4] = {ox4[j].x, ox4[j].y, ox4[j].z, ox4[j].w};

        float pw[4], w0[4], w1[4];
        #pragma unroll
        for (int k = 0; k < 4; ++k) {
            const unsigned s = (packed[j] >> (8 * k)) & 0xFFu;
            const int g = (int)(s & 0xFu);
            const float wraw = inv_sh[g];                      // bank-conflict-free
            const float w = (s & 0x10u) ? wraw : 0.0f;
            const float agree_w = ((int)(tb[j][k] & 0xFu) == g) ? w : 0.0f;
            pw[k] = w * sigmoidf_fast(prs[k]);
            w0[k] = agree_w * oys[k];
            w1[k] = agree_w * oxs[k];
        }

        *reinterpret_cast<float4*>(out_pw_b + rem)             = make_float4(pw[0], pw[1], pw[2], pw[3]);
        *reinterpret_cast<float4*>(out_ow_b + rem)             = make_float4(w0[0], w0[1], w0[2], w0[3]);
        *reinterpret_cast<float4*>(out_ow_b + rem + PER_BATCH) = make_float4(w1[0], w1[1], w1[2], w1[3]);
    }

    // Replay-safe cleanup: the 4096th arrival zeroes g_cnt for the next launch.
    // Every block increments only after its g_cnt read was consumed (sync above),
    // so "all arrived" implies "all have read" — no race.
    if (threadIdx.x == 0) {
        const unsigned long long old = atomicAdd(&g_done, 1ULL);
        last = ((old & (unsigned long long)(GRID3 - 1)) == (unsigned long long)(GRID3 - 1));
    }
    __syncthreads();
    if (last && threadIdx.x < BATCH * MAX_INST) g_cnt[threadIdx.x] = 0;
}

extern "C" void kernel_launch(void* const* d_in, const int* in_sizes, int n_in,
                              void* d_out, int out_size) {
    const int*   nz   = (const int*)  d_in[0];  // non_zeros_map (B,R,C) int32
    const float* pred = (const float*)d_in[1];  // pixel_pred    (B,R,C) f32
    const float* off  = (const float*)d_in[2];  // offset_pred   (B,2,R,C) f32
    const int*   gt   = (const int*)  d_in[3];  // pixel_gt      (B,R,C) int32

    const long long N = in_sizes[0];            // B*R*C
    float* out_pw = (float*)d_out;
    float* out_ow = (float*)d_out + N;

    dim3 grid1(BLKS_PER_B, BATCH);
    pc_count_kernel<<<grid1, TPB1>>>(nz, gt);
    pc_main_kernel<<<GRID3, TPB3>>>(pred, off, out_pw, out_ow);
}

// round 12
// speedup vs baseline: 1.0379x; 1.0379x over previous
#include <cuda_runtime.h>
#include <cuda_bf16.h>

// Fixed problem shape: B=8, R=C=1024, instance ids in [0,16).
static constexpr int RDIM = 1024;
static constexpr int CDIM = 1024;
static constexpr int PER_BATCH = RDIM * CDIM;            // 2^20 pixels
static constexpr int BATCH = 8;
static constexpr int MAX_INST = 16;
static constexpr int NPIX = BATCH * PER_BATCH;           // 2^23
static constexpr int NVEC_B = PER_BATCH / 4;             // 2^18 vec4 per batch

// Kernel 1: 256 threads x 4 vec4/thread, front-loaded loads (R6-proven).
static constexpr int TPB1 = 256;
static constexpr int VPT1 = 4;
static constexpr int VEC_PER_BLK1 = TPB1 * VPT1;                    // 1024
static constexpr int BLKS_PER_B = NVEC_B / VEC_PER_BLK1;            // 256
// Kernel 2 (main): 2 vec4/thread, batch-pure blocks.
static constexpr int TPB3 = 256;
static constexpr int VPT3 = 2;
static constexpr int GRID3 = (NPIX / 4) / (TPB3 * VPT3);            // 4096

// Scratch (static device globals; zero-initialized at module load).
// Invariant: g_cnt == 0 at the start of every kernel_launch execution —
// the LAST main block re-zeroes it after all blocks consumed it.
__device__ int                g_cnt[BATCH * MAX_INST];
__device__ unsigned long long g_done;          // monotone arrival counter
__device__ unsigned char      g_plane[NPIX];   // byte = raw_gt | (valid << 4)

__device__ __forceinline__ float sigmoidf_fast(float x) {
    return 1.0f / (1.0f + __expf(-x));
}

__device__ __forceinline__ float4 ldcs4(const float* p) {
    return __ldcs(reinterpret_cast<const float4*>(p));
}

// ---- Kernel 1: counts (atomic accumulate) + combined byte plane ----
__global__ void __launch_bounds__(TPB1, 4) pc_count_kernel(
    const int* __restrict__ nz, const int* __restrict__ gt)
{
    __shared__ unsigned long long wcnt[TPB1 / 32][4];

    const int tid  = threadIdx.x;
    const int wid  = tid >> 5;
    const int lane = tid & 31;
    const int b    = blockIdx.y;
    const long long base = ((long long)b << 20)
                         + (long long)(blockIdx.x * VEC_PER_BLK1 + tid) * 4;

    // Front-load ALL global reads: 8 outstanding LDG.128 before any compute.
    // Read-once streams -> evict-first policy.
    int4 nzv[VPT1], gtv[VPT1];
    #pragma unroll
    for (int j = 0; j < VPT1; ++j) {
        const long long i0 = base + (long long)j * (TPB1 * 4);
        nzv[j] = __ldcs(reinterpret_cast<const int4*>(nz + i0));
        gtv[j] = __ldcs(reinterpret_cast<const int4*>(gt + i0));
    }

    // Two independent 4-bit-field accumulators (id*4 bit position).
    unsigned long long c01 = 0ULL, c23 = 0ULL;

    #pragma unroll
    for (int j = 0; j < VPT1; ++j) {
        const long long i0 = base + (long long)j * (TPB1 * 4);
        const unsigned g01 = __byte_perm((unsigned)gtv[j].x, (unsigned)gtv[j].y, 0x0040);
        const unsigned g23 = __byte_perm((unsigned)gtv[j].z, (unsigned)gtv[j].w, 0x0040);
        const unsigned gp  = __byte_perm(g01, g23, 0x5410);
        const unsigned n01 = __byte_perm((unsigned)nzv[j].x, (unsigned)nzv[j].y, 0x0040);
        const unsigned n23 = __byte_perm((unsigned)nzv[j].z, (unsigned)nzv[j].w, 0x0040);
        const unsigned np  = __byte_perm(n01, n23, 0x5410);

        const unsigned vmask = ((gp + 0x0F0F0F0Fu) & 0x10101010u) & (np << 4);
        // plane is re-read by the main kernel -> default policy (stay in L2)
        *reinterpret_cast<unsigned int*>(g_plane + i0) = gp | vmask;

        const unsigned mg = gp & ((vmask >> 4) * 0xFFu);

        unsigned long long& c = (j < 2) ? c01 : c23;
        c += 1ULL << ((mg << 2) & 0x3Cu);
        c += 1ULL << ((mg >> 6) & 0x3Cu);
        c += 1ULL << ((mg >> 14) & 0x3Cu);
        c += 1ULL << ((mg >> 22) & 0x3Cu);
    }

    const unsigned long long M4 = 0x0F0F0F0F0F0F0F0FULL;
    const unsigned long long M8 = 0x00FF00FF00FF00FFULL;
    const unsigned long long A  = (c01 & M4) + (c23 & M4);
    const unsigned long long Bv = ((c01 >> 4) & M4) + ((c23 >> 4) & M4);
    unsigned long long v0 = A & M8;          // ids 0,4,8,12
    unsigned long long v1 = (A >> 8) & M8;   // ids 2,6,10,14
    unsigned long long v2 = Bv & M8;         // ids 1,5,9,13
    unsigned long long v3 = (Bv >> 8) & M8;  // ids 3,7,11,15

    #pragma unroll
    for (int s = 16; s > 0; s >>= 1) {
        v0 += __shfl_xor_sync(0xffffffffu, v0, s);
        v1 += __shfl_xor_sync(0xffffffffu, v1, s);
        v2 += __shfl_xor_sync(0xffffffffu, v2, s);
        v3 += __shfl_xor_sync(0xffffffffu, v3, s);
    }
    if (lane == 0) {
        wcnt[wid][0] = v0; wcnt[wid][1] = v1; wcnt[wid][2] = v2; wcnt[wid][3] = v3;
    }
    __syncthreads();

    if (tid < MAX_INST) {
        const int id = tid;
        const int vec   = (id & 1) ? ((id & 2) ? 3 : 2) : ((id & 2) ? 1 : 0);
        const int shift = (id >> 2) * 16;
        int s = 0;
        #pragma unroll
        for (int w = 0; w < TPB1 / 32; ++w)
            s += (int)((wcnt[w][vec] >> shift) & 0xFFFFULL);
        atomicAdd(&g_cnt[b * MAX_INST + id], s);   // L2-coherent; no fence needed
    }
}

// ---- Kernel 2: per-pixel weights; per-block inv table from g_cnt;
//      last block zeroes g_cnt for the next graph replay. ----
__global__ void __launch_bounds__(TPB3) pc_main_kernel(
    const float* __restrict__ pred,
    const float* __restrict__ off,     // (B, 2, R, C)
    float*       __restrict__ out_pw,  // (B, R, C)
    float*       __restrict__ out_ow)  // (B, 2, R, C)
{
    __shared__ float inv_sh[MAX_INST];
    __shared__ bool  last;

    const int vblk = blockIdx.x * (TPB3 * VPT3);           // block never straddles a batch
    const int b    = vblk >> 18;                           // / (PER_BATCH/4)
    const unsigned rem0 = (unsigned)((vblk + threadIdx.x) << 2) & (PER_BATCH - 1);

    // Build this batch's inv table (one 64B L2-hot line).
    if (threadIdx.x < MAX_INST) {
        const int c = g_cnt[b * MAX_INST + threadIdx.x];
        inv_sh[threadIdx.x] = 1.0f / fmaxf((float)c, 1.0f);
    }
    __syncthreads();

    const float* __restrict__ pred_b   = pred   + ((long long)b << 20);
    const float* __restrict__ off_b    = off    + ((long long)b << 21);
    float*       __restrict__ out_pw_b = out_pw + ((long long)b << 20);
    float*       __restrict__ out_ow_b = out_ow + ((long long)b << 21);
    const unsigned char* __restrict__ plane_b = g_plane + ((long long)b << 20);

    // Stage 1: front-load all streaming reads (evict-first; 10 outstanding LDGs).
    unsigned int packed[VPT3];
    float4 pr4[VPT3], oy4[VPT3], ox4[VPT3];
    #pragma unroll
    for (int j = 0; j < VPT3; ++j) {
        const unsigned rem = rem0 + j * (TPB3 * 4);
        packed[j] = __ldcs(reinterpret_cast<const unsigned int*>(plane_b + rem));
        oy4[j] = ldcs4(off_b + rem);
        ox4[j] = ldcs4(off_b + rem + PER_BATCH);
        pr4[j] = ldcs4(pred_b + rem);
    }

    // Stage 2: all 8 gather addresses, all gathers issued in parallel.
    // Gathers use default policy: keep the 8MB plane resident in L2.
    unsigned tb[VPT3][4];
    #pragma unroll
    for (int j = 0; j < VPT3; ++j) {
        const unsigned rem = rem0 + j * (TPB3 * 4);
        const float rf = (float)(rem >> 10);
        const float cf = (float)(rem & (CDIM - 1));
        const float oys[4] = {oy4[j].x, oy4[j].y, oy4[j].z, oy4[j].w};
        const float oxs[4] = {ox4[j].x, ox4[j].y, ox4[j].z, ox4[j].w};
        #pragma unroll
        for (int k = 0; k < 4; ++k) {
            // round-half-to-even matches jnp.round
            float tyf = rintf(rf + oys[k]);
            float txf = rintf(cf + (float)k + oxs[k]);
            tyf = fminf(fmaxf(tyf, 0.0f), (float)(RDIM - 1));
            txf = fminf(fmaxf(txf, 0.0f), (float)(CDIM - 1));
            tb[j][k] = __ldg(&plane_b[((unsigned)tyf << 10) + (unsigned)txf]);
        }
    }

    // Stage 3: straight-line epilogue; write-once outputs -> evict-first stores.
    #pragma unroll
    for (int j = 0; j < VPT3; ++j) {
        const unsigned rem = rem0 + j * (TPB3 * 4);
        const float prs[4] = {pr4[j].x, pr4[j].y, pr4[j].z, pr4[j].w};
        const float oys[4] = {oy4[j].x, oy4[j].y, oy4[j].z, oy4[j].w};
        const float oxs[4] = {ox4[j].x, ox4[j].y, ox4[j].z, ox4[j].w};

        float pw[4], w0[4], w1[4];
        #pragma unroll
        for (int k = 0; k < 4; ++k) {
            const unsigned s = (packed[j] >> (8 * k)) & 0xFFu;
            const int g = (int)(s & 0xFu);
            const float wraw = inv_sh[g];                      // bank-conflict-free
            const float w = (s & 0x10u) ? wraw : 0.0f;
            const float agree_w = ((int)(tb[j][k] & 0xFu) == g) ? w : 0.0f;
            pw[k] = w * sigmoidf_fast(prs[k]);
            w0[k] = agree_w * oys[k];
            w1[k] = agree_w * oxs[k];
        }

        __stcs(reinterpret_cast<float4*>(out_pw_b + rem),
               make_float4(pw[0], pw[1], pw[2], pw[3]));
        __stcs(reinterpret_cast<float4*>(out_ow_b + rem),
               make_float4(w0[0], w0[1], w0[2], w0[3]));
        __stcs(reinterpret_cast<float4*>(out_ow_b + rem + PER_BATCH),
               make_float4(w1[0], w1[1], w1[2], w1[3]));
    }

    // Replay-safe cleanup: the 4096th arrival zeroes g_cnt for the next launch.
    // Every block increments only after its g_cnt read was consumed (sync above),
    // so "all arrived" implies "all have read" — no race.
    if (threadIdx.x == 0) {
        const unsigned long long old = atomicAdd(&g_done, 1ULL);
        last = ((old & (unsigned long long)(GRID3 - 1)) == (unsigned long long)(GRID3 - 1));
    }
    __syncthreads();
    if (last && threadIdx.x < BATCH * MAX_INST) g_cnt[threadIdx.x] = 0;
}

extern "C" void kernel_launch(void* const* d_in, const int* in_sizes, int n_in,
                              void* d_out, int out_size) {
    const int*   nz   = (const int*)  d_in[0];  // non_zeros_map (B,R,C) int32
    const float* pred = (const float*)d_in[1];  // pixel_pred    (B,R,C) f32
    const float* off  = (const float*)d_in[2];  // offset_pred   (B,2,R,C) f32
    const int*   gt   = (const int*)  d_in[3];  // pixel_gt      (B,R,C) int32

    const long long N = in_sizes[0];            // B*R*C
    float* out_pw = (float*)d_out;
    float* out_ow = (float*)d_out + N;

    dim3 grid1(BLKS_PER_B, BATCH);
    pc_count_kernel<<<grid1, TPB1>>>(nz, gt);
    pc_main_kernel<<<GRID3, TPB3>>>(pred, off, out_pw, out_ow);
}

// round 13
// speedup vs baseline: 1.0504x; 1.0120x over previous
#include <cuda_runtime.h>
#include <cuda_bf16.h>

// Fixed problem shape: B=8, R=C=1024, instance ids in [0,16).
static constexpr int RDIM = 1024;
static constexpr int CDIM = 1024;
static constexpr int PER_BATCH = RDIM * CDIM;            // 2^20 pixels
static constexpr int BATCH = 8;
static constexpr int MAX_INST = 16;
static constexpr int NPIX = BATCH * PER_BATCH;           // 2^23
static constexpr int NVEC_B = PER_BATCH / 4;             // 2^18 vec4 per batch

// Kernel 1: 256 threads x 4 vec4/thread, front-loaded loads (R6-proven).
static constexpr int TPB1 = 256;
static constexpr int VPT1 = 4;
static constexpr int VEC_PER_BLK1 = TPB1 * VPT1;                    // 1024
static constexpr int BLKS_PER_B = NVEC_B / VEC_PER_BLK1;            // 256
// Kernel 2 (main): 2 vec4/thread, batch-pure blocks.
static constexpr int TPB3 = 256;
static constexpr int VPT3 = 2;
static constexpr int GRID3 = (NPIX / 4) / (TPB3 * VPT3);            // 4096

// Scratch (static device globals; zero-initialized at module load).
// Invariant: g_cnt == 0 at the start of every kernel_launch execution —
// the LAST main block re-zeroes it after all blocks consumed it.
__device__ int                g_cnt[BATCH * MAX_INST];
__device__ unsigned long long g_done;          // monotone arrival counter
__device__ unsigned char      g_plane[NPIX];   // byte = raw_gt | (valid << 4)

__device__ __forceinline__ float sigmoidf_fast(float x) {
    return 1.0f / (1.0f + __expf(-x));
}

__device__ __forceinline__ float4 ldcs4(const float* p) {
    return __ldcs(reinterpret_cast<const float4*>(p));
}

// ---- Kernel 1: counts (atomic accumulate) + combined byte plane ----
__global__ void __launch_bounds__(TPB1, 4) pc_count_kernel(
    const int* __restrict__ nz, const int* __restrict__ gt)
{
    __shared__ unsigned long long wcnt[TPB1 / 32][4];

    const int tid  = threadIdx.x;
    const int wid  = tid >> 5;
    const int lane = tid & 31;
    const int b    = blockIdx.y;
    const long long base = ((long long)b << 20)
                         + (long long)(blockIdx.x * VEC_PER_BLK1 + tid) * 4;

    // Front-load ALL global reads: 8 outstanding LDG.128 before any compute.
    int4 nzv[VPT1], gtv[VPT1];
    #pragma unroll
    for (int j = 0; j < VPT1; ++j) {
        const long long i0 = base + (long long)j * (TPB1 * 4);
        nzv[j] = *reinterpret_cast<const int4*>(nz + i0);
        gtv[j] = *reinterpret_cast<const int4*>(gt + i0);
    }

    // Two independent 4-bit-field accumulators (id*4 bit position).
    unsigned long long c01 = 0ULL, c23 = 0ULL;

    #pragma unroll
    for (int j = 0; j < VPT1; ++j) {
        const long long i0 = base + (long long)j * (TPB1 * 4);
        const unsigned g01 = __byte_perm((unsigned)gtv[j].x, (unsigned)gtv[j].y, 0x0040);
        const unsigned g23 = __byte_perm((unsigned)gtv[j].z, (unsigned)gtv[j].w, 0x0040);
        const unsigned gp  = __byte_perm(g01, g23, 0x5410);
        const unsigned n01 = __byte_perm((unsigned)nzv[j].x, (unsigned)nzv[j].y, 0x0040);
        const unsigned n23 = __byte_perm((unsigned)nzv[j].z, (unsigned)nzv[j].w, 0x0040);
        const unsigned np  = __byte_perm(n01, n23, 0x5410);

        const unsigned vmask = ((gp + 0x0F0F0F0Fu) & 0x10101010u) & (np << 4);
        // plane is re-read by the main kernel -> default policy (stay in L2)
        *reinterpret_cast<unsigned int*>(g_plane + i0) = gp | vmask;

        const unsigned mg = gp & ((vmask >> 4) * 0xFFu);

        unsigned long long& c = (j < 2) ? c01 : c23;
        c += 1ULL << ((mg << 2) & 0x3Cu);
        c += 1ULL << ((mg >> 6) & 0x3Cu);
        c += 1ULL << ((mg >> 14) & 0x3Cu);
        c += 1ULL << ((mg >> 22) & 0x3Cu);
    }

    const unsigned long long M4 = 0x0F0F0F0F0F0F0F0FULL;
    const unsigned long long M8 = 0x00FF00FF00FF00FFULL;
    const unsigned long long A  = (c01 & M4) + (c23 & M4);
    const unsigned long long Bv = ((c01 >> 4) & M4) + ((c23 >> 4) & M4);
    unsigned long long v0 = A & M8;          // ids 0,4,8,12
    unsigned long long v1 = (A >> 8) & M8;   // ids 2,6,10,14
    unsigned long long v2 = Bv & M8;         // ids 1,5,9,13
    unsigned long long v3 = (Bv >> 8) & M8;  // ids 3,7,11,15

    #pragma unroll
    for (int s = 16; s > 0; s >>= 1) {
        v0 += __shfl_xor_sync(0xffffffffu, v0, s);
        v1 += __shfl_xor_sync(0xffffffffu, v1, s);
        v2 += __shfl_xor_sync(0xffffffffu, v2, s);
        v3 += __shfl_xor_sync(0xffffffffu, v3, s);
    }
    if (lane == 0) {
        wcnt[wid][0] = v0; wcnt[wid][1] = v1; wcnt[wid][2] = v2; wcnt[wid][3] = v3;
    }
    __syncthreads();

    if (tid < MAX_INST) {
        const int id = tid;
        const int vec   = (id & 1) ? ((id & 2) ? 3 : 2) : ((id & 2) ? 1 : 0);
        const int shift = (id >> 2) * 16;
        int s = 0;
        #pragma unroll
        for (int w = 0; w < TPB1 / 32; ++w)
            s += (int)((wcnt[w][vec] >> shift) & 0xFFFFULL);
        atomicAdd(&g_cnt[b * MAX_INST + id], s);   // L2-coherent; no fence needed
    }
}

// ---- Kernel 2: per-pixel weights; per-block inv table from g_cnt;
//      last block zeroes g_cnt for the next graph replay. ----
__global__ void __launch_bounds__(TPB3) pc_main_kernel(
    const float* __restrict__ pred,
    const float* __restrict__ off,     // (B, 2, R, C)
    float*       __restrict__ out_pw,  // (B, R, C)
    float*       __restrict__ out_ow)  // (B, 2, R, C)
{
    __shared__ float inv_sh[MAX_INST];
    __shared__ bool  last;

    const int vblk = blockIdx.x * (TPB3 * VPT3);           // block never straddles a batch
    const int b    = vblk >> 18;                           // / (PER_BATCH/4)
    const unsigned rem0 = (unsigned)((vblk + threadIdx.x) << 2) & (PER_BATCH - 1);

    // Build this batch's inv table (one 64B L2-hot line).
    if (threadIdx.x < MAX_INST) {
        const int c = g_cnt[b * MAX_INST + threadIdx.x];
        inv_sh[threadIdx.x] = 1.0f / fmaxf((float)c, 1.0f);
    }
    __syncthreads();

    const float* __restrict__ pred_b   = pred   + ((long long)b << 20);
    const float* __restrict__ off_b    = off    + ((long long)b << 21);
    float*       __restrict__ out_pw_b = out_pw + ((long long)b << 20);
    float*       __restrict__ out_ow_b = out_ow + ((long long)b << 21);
    const unsigned char* __restrict__ plane_b = g_plane + ((long long)b << 20);

    // Stage 1: front-load all streaming reads (10 outstanding LDGs).
    // pred/off are read-once -> evict-first. packed stays default: its lines
    // are the very lines neighboring blocks gather from.
    unsigned int packed[VPT3];
    float4 pr4[VPT3], oy4[VPT3], ox4[VPT3];
    #pragma unroll
    for (int j = 0; j < VPT3; ++j) {
        const unsigned rem = rem0 + j * (TPB3 * 4);
        packed[j] = *reinterpret_cast<const unsigned int*>(plane_b + rem);
        oy4[j] = ldcs4(off_b + rem);
        ox4[j] = ldcs4(off_b + rem + PER_BATCH);
        pr4[j] = ldcs4(pred_b + rem);
    }

    // Stage 2: all 8 gather addresses via short int chains, gathers in parallel.
    unsigned tb[VPT3][4];
    #pragma unroll
    for (int j = 0; j < VPT3; ++j) {
        const unsigned rem = rem0 + j * (TPB3 * 4);
        const float rf = (float)(rem >> 10);
        const float cf = (float)(rem & (CDIM - 1));
        const float oys[4] = {oy4[j].x, oy4[j].y, oy4[j].z, oy4[j].w};
        const float oxs[4] = {ox4[j].x, ox4[j].y, ox4[j].z, ox4[j].w};
        #pragma unroll
        for (int k = 0; k < 4; ++k) {
            // __float2int_rn = round-half-to-even, matches jnp.round; clamp in int.
            int ty = __float2int_rn(rf + oys[k]);
            int tx = __float2int_rn(cf + (float)k + oxs[k]);
            ty = min(max(ty, 0), RDIM - 1);
            tx = min(max(tx, 0), CDIM - 1);
            tb[j][k] = __ldg(&plane_b[((unsigned)ty << 10) + (unsigned)tx]);
        }
    }

    // Stage 3: straight-line epilogue; write-once outputs -> evict-first stores.
    #pragma unroll
    for (int j = 0; j < VPT3; ++j) {
        const unsigned rem = rem0 + j * (TPB3 * 4);
        const float prs[4] = {pr4[j].x, pr4[j].y, pr4[j].z, pr4[j].w};
        const float oys[4] = {oy4[j].x, oy4[j].y, oy4[j].z, oy4[j].w};
        const float oxs[4] = {ox4[j].x, ox4[j].y, ox4[j].z, ox4[j].w};

        float pw[4], w0[4], w1[4];
        #pragma unroll
        for (int k = 0; k < 4; ++k) {
            const unsigned s = (packed[j] >> (8 * k)) & 0xFFu;
            const int g = (int)(s & 0xFu);
            const float wraw = inv_sh[g];                      // bank-conflict-free
            const float w = (s & 0x10u) ? wraw : 0.0f;
            const float agree_w = ((int)(tb[j][k] & 0xFu) == g) ? w : 0.0f;
            pw[k] = w * sigmoidf_fast(prs[k]);
            w0[k] = agree_w * oys[k];
            w1[k] = agree_w * oxs[k];
        }

        __stcs(reinterpret_cast<float4*>(out_pw_b + rem),
               make_float4(pw[0], pw[1], pw[2], pw[3]));
        __stcs(reinterpret_cast<float4*>(out_ow_b + rem),
               make_float4(w0[0], w0[1], w0[2], w0[3]));
        __stcs(reinterpret_cast<float4*>(out_ow_b + rem + PER_BATCH),
               make_float4(w1[0], w1[1], w1[2], w1[3]));
    }

    // Replay-safe cleanup: the 4096th arrival zeroes g_cnt for the next launch.
    // Every block increments only after its g_cnt read was consumed (sync above),
    // so "all arrived" implies "all have read" — no race.
    if (threadIdx.x == 0) {
        const unsigned long long old = atomicAdd(&g_done, 1ULL);
        last = ((old & (unsigned long long)(GRID3 - 1)) == (unsigned long long)(GRID3 - 1));
    }
    __syncthreads();
    if (last && threadIdx.x < BATCH * MAX_INST) g_cnt[threadIdx.x] = 0;
}

extern "C" void kernel_launch(void* const* d_in, const int* in_sizes, int n_in,
                              void* d_out, int out_size) {
    const int*   nz   = (const int*)  d_in[0];  // non_zeros_map (B,R,C) int32
    const float* pred = (const float*)d_in[1];  // pixel_pred    (B,R,C) f32
    const float* off  = (const float*)d_in[2];  // offset_pred   (B,2,R,C) f32
    const int*   gt   = (const int*)  d_in[3];  // pixel_gt      (B,R,C) int32

    const long long N = in_sizes[0];            // B*R*C
    float* out_pw = (float*)d_out;
    float* out_ow = (float*)d_out + N;

    dim3 grid1(BLKS_PER_B, BATCH);
    pc_count_kernel<<<grid1, TPB1>>>(nz, gt);
    pc_main_kernel<<<GRID3, TPB3>>>(pred, off, out_pw, out_ow);
}